// round 2
// baseline (speedup 1.0000x reference)
#include <cuda_runtime.h>

#define N_NODES 50000
#define N_EDGES 640000
#define D 128

// ---------------- scratch (device globals; no allocs allowed) ----------------
__device__ float g_h[3][N_NODES * D];   // layer outputs h1,h2,h3
__device__ float g_t[N_NODES * D];      // (1+eps)*h + agg
__device__ float g_z[N_NODES * D];      // mid-MLP
__device__ int   g_rowptr[N_NODES + 1];
__device__ int   g_cnt[N_NODES];
__device__ int   g_srcs[N_EDGES];
__device__ int   g_is64;                // 1 if edge_index is int64, 0 if int32

// buffer selectors (avoid cudaGetSymbolAddress under graph capture)
#define SEL_X   0
#define SEL_T   1
#define SEL_Z   2
#define SEL_H0  3
#define SEL_H1  4
#define SEL_H2  5
#define SEL_OUT 6

__device__ __forceinline__ float* sel_buf(int sel, const float* x, float* out) {
    switch (sel) {
        case SEL_X:  return (float*)x;
        case SEL_T:  return g_t;
        case SEL_Z:  return g_z;
        case SEL_H0: return g_h[0];
        case SEL_H1: return g_h[1];
        case SEL_H2: return g_h[2];
        default:     return out;
    }
}

// ---------------- edge dtype detection ----------------
// int64 little-endian with values < 2^31: every odd int32 word is 0.
// int32 real data: odd words are uniform in [0, 50000) -> all-zero over 64
// samples has probability ~0.
__global__ void detect_kernel(const int* __restrict__ ei32) {
    if (threadIdx.x == 0 && blockIdx.x == 0) {
        int ornz = 0;
#pragma unroll
        for (int i = 0; i < 64; i++) ornz |= ei32[2 * i + 1];
        g_is64 = (ornz == 0) ? 1 : 0;
    }
}

__device__ __forceinline__ int edge_val(const int* ei32, int is64, long long idx) {
    return is64 ? ei32[2 * idx] : ei32[idx];
}

// ---------------- CSR build ----------------
__global__ void zero_cnt_kernel() {
    int i = blockIdx.x * blockDim.x + threadIdx.x;
    if (i < N_NODES) g_cnt[i] = 0;
}

__global__ void hist_kernel(const int* __restrict__ ei32) {
    int e = blockIdx.x * blockDim.x + threadIdx.x;
    if (e < N_EDGES) {
        int is64 = g_is64;
        int dst = edge_val(ei32, is64, (long long)N_EDGES + e);
        if ((unsigned)dst < (unsigned)N_NODES) atomicAdd(&g_cnt[dst], 1);
    }
}

__global__ void scan_kernel() {
    __shared__ int part[1024];
    const int tid = threadIdx.x;
    const int CH = (N_NODES + 1023) / 1024;
    int start = tid * CH;
    int end = start + CH;
    if (end > N_NODES) end = N_NODES;
    int s = 0;
    if (start < N_NODES)
        for (int i = start; i < end; i++) s += g_cnt[i];
    part[tid] = s;
    __syncthreads();
    for (int off = 1; off < 1024; off <<= 1) {
        int v = 0;
        if (tid >= off) v = part[tid - off];
        __syncthreads();
        part[tid] += v;
        __syncthreads();
    }
    int run = part[tid] - s;  // exclusive prefix
    if (start < N_NODES)
        for (int i = start; i < end; i++) { g_rowptr[i] = run; run += g_cnt[i]; }
    if (tid == 0) g_rowptr[N_NODES] = part[1023];
}

__global__ void scatter_kernel(const int* __restrict__ ei32) {
    int e = blockIdx.x * blockDim.x + threadIdx.x;
    if (e < N_EDGES) {
        int is64 = g_is64;
        int src = edge_val(ei32, is64, e);
        int dst = edge_val(ei32, is64, (long long)N_EDGES + e);
        if ((unsigned)dst < (unsigned)N_NODES && (unsigned)src < (unsigned)N_NODES) {
            int pos = g_rowptr[dst] + atomicAdd(&g_cnt[dst], 1);
            if ((unsigned)pos < (unsigned)N_EDGES) g_srcs[pos] = src;
        }
    }
}

// ---------------- aggregation: t = (1+eps[l])*h + segment_sum(h[src]) --------
__global__ void agg_kernel(int hin_sel, const float* __restrict__ x,
                           const float* __restrict__ eps, int l) {
    const float* h = sel_buf(hin_sel, x, nullptr);
    int w = (blockIdx.x * blockDim.x + threadIdx.x) >> 5;
    int lane = threadIdx.x & 31;
    if (w >= N_NODES) return;
    int beg = g_rowptr[w], end = g_rowptr[w + 1];
    const float4* hp = (const float4*)h;
    float4 acc = make_float4(0.f, 0.f, 0.f, 0.f);
    for (int i = beg; i < end; i++) {
        int s = g_srcs[i];
        float4 v = __ldg(&hp[s * 32 + lane]);
        acc.x += v.x; acc.y += v.y; acc.z += v.z; acc.w += v.w;
    }
    float e = 1.0f + eps[l];
    float4 hv = hp[w * 32 + lane];
    float4 o = make_float4(fmaf(e, hv.x, acc.x), fmaf(e, hv.y, acc.y),
                           fmaf(e, hv.z, acc.z), fmaf(e, hv.w, acc.w));
    ((float4*)g_t)[w * 32 + lane] = o;
}

// ---------------- GEMM: out = [relu]( A[M,128] @ W[128,128] + bias ) ---------
// flags: 1 = relu, 2 = add bias, 4 = accumulate into out
#define FLAG_RELU 1
#define FLAG_BIAS 2
#define FLAG_ACC  4

__device__ __forceinline__ unsigned long long ffma2(unsigned long long a,
                                                    unsigned long long b,
                                                    unsigned long long c) {
    asm("fma.rn.f32x2 %0, %1, %2, %0;" : "+l"(c) : "l"(a), "l"(b));
    return c;
}

__global__ void __launch_bounds__(256, 2)
gemm128_kernel(int a_sel, const float* __restrict__ W,
               const float* __restrict__ bias, int o_sel, int flags,
               const float* __restrict__ x, float* __restrict__ dout) {
    __shared__ float As[128][36];   // BM x BK (+pad)
    __shared__ float Ws[32][128];   // BK x BN

    const float* A = sel_buf(a_sel, x, dout);
    float* out = sel_buf(o_sel, x, dout);

    const int tid = threadIdx.x;
    const int tx = tid & 15;        // 0..15 -> 8 cols each
    const int ty = tid >> 4;        // 0..15 -> 8 rows each
    const int rowBase = blockIdx.x * 128;
    const int M = N_NODES;

    unsigned long long acc[8][4];
#pragma unroll
    for (int i = 0; i < 8; i++)
#pragma unroll
        for (int j = 0; j < 4; j++) acc[i][j] = 0ULL;

    const int ar  = tid >> 3;          // 0..31 (A tile row within pass)
    const int ac4 = (tid & 7) << 2;    // 0,4,...,28
    const int wr  = tid >> 5;          // 0..7
    const int wc4 = (tid & 31) << 2;   // 0..124

    for (int kc = 0; kc < 128; kc += 32) {
        // load A tile 128x32
#pragma unroll
        for (int rr = 0; rr < 128; rr += 32) {
            int row = rowBase + rr + ar;
            float4 v = make_float4(0.f, 0.f, 0.f, 0.f);
            if (row < M) v = *(const float4*)&A[row * 128 + kc + ac4];
            *(float4*)&As[rr + ar][ac4] = v;
        }
        // load W tile 32x128
#pragma unroll
        for (int rr = 0; rr < 32; rr += 8) {
            *(float4*)&Ws[rr + wr][wc4] =
                *(const float4*)&W[(kc + rr + wr) * 128 + wc4];
        }
        __syncthreads();

#pragma unroll
        for (int k = 0; k < 32; k++) {
            unsigned long long bp[4];
            {
                const ulonglong2* wp = (const ulonglong2*)&Ws[k][tx << 3];
                ulonglong2 b0 = wp[0];
                ulonglong2 b1 = wp[1];
                bp[0] = b0.x; bp[1] = b0.y; bp[2] = b1.x; bp[3] = b1.y;
            }
#pragma unroll
            for (int i = 0; i < 8; i++) {
                unsigned int au = __float_as_uint(As[(ty << 3) + i][k]);
                unsigned long long ad;
                asm("mov.b64 %0, {%1, %2};" : "=l"(ad) : "r"(au), "r"(au));
#pragma unroll
                for (int j = 0; j < 4; j++) acc[i][j] = ffma2(ad, bp[j], acc[i][j]);
            }
        }
        __syncthreads();
    }

    const bool relu  = (flags & FLAG_RELU) != 0;
    const bool addb  = (flags & FLAG_BIAS) != 0;
    const bool accum = (flags & FLAG_ACC) != 0;

    float bvals[8];
#pragma unroll
    for (int j = 0; j < 8; j++) bvals[j] = addb ? bias[(tx << 3) + j] : 0.f;

#pragma unroll
    for (int i = 0; i < 8; i++) {
        int row = rowBase + (ty << 3) + i;
        if (row < M) {
            float o[8];
#pragma unroll
            for (int j = 0; j < 4; j++) {
                float2 p = *(float2*)&acc[i][j];
                o[2 * j] = p.x; o[2 * j + 1] = p.y;
            }
            float* op = &out[row * 128 + (tx << 3)];
            if (accum) {
                float4 e0 = *(float4*)&op[0];
                float4 e1 = *(float4*)&op[4];
                o[0] += e0.x; o[1] += e0.y; o[2] += e0.z; o[3] += e0.w;
                o[4] += e1.x; o[5] += e1.y; o[6] += e1.z; o[7] += e1.w;
            }
#pragma unroll
            for (int j = 0; j < 8; j++) {
                o[j] += bvals[j];
                if (relu) o[j] = fmaxf(o[j], 0.f);
            }
            *(float4*)&op[0] = make_float4(o[0], o[1], o[2], o[3]);
            *(float4*)&op[4] = make_float4(o[4], o[5], o[6], o[7]);
        }
    }
}

// ---------------- launch ----------------
extern "C" void kernel_launch(void* const* d_in, const int* in_sizes, int n_in,
                              void* d_out, int out_size) {
    const float* x   = (const float*)d_in[0];
    const int*   ei  = (const int*)d_in[1];    // int32 view; dtype detected on device
    const float* W1  = (const float*)d_in[2];
    const float* b1  = (const float*)d_in[3];
    const float* W2  = (const float*)d_in[4];
    const float* b2  = (const float*)d_in[5];
    const float* eps = (const float*)d_in[6];
    const float* fw  = (const float*)d_in[7];
    const float* fb  = (const float*)d_in[8];
    float* out = (float*)d_out;

    const int ZB = (N_NODES + 255) / 256;
    const int EB = (N_EDGES + 255) / 256;
    const int GB = (N_NODES + 127) / 128;       // 391 GEMM row-blocks
    const int AB = (N_NODES * 32 + 255) / 256;  // one warp per node

    // build CSR (dst is call-invariant; rebuild every call for determinism rules)
    detect_kernel<<<1, 32>>>(ei);
    zero_cnt_kernel<<<ZB, 256>>>();
    hist_kernel<<<EB, 256>>>(ei);
    scan_kernel<<<1, 1024>>>();
    zero_cnt_kernel<<<ZB, 256>>>();
    scatter_kernel<<<EB, 256>>>(ei);

    // 3 GIN layers
    int hin[3]  = { SEL_X, SEL_H0, SEL_H1 };
    int hout[3] = { SEL_H0, SEL_H1, SEL_H2 };
    for (int l = 0; l < 3; l++) {
        agg_kernel<<<AB, 256>>>(hin[l], x, eps, l);
        gemm128_kernel<<<GB, 256>>>(SEL_T, W1 + l * 128 * 128, b1 + l * 128,
                                    SEL_Z, FLAG_RELU | FLAG_BIAS, x, out);
        gemm128_kernel<<<GB, 256>>>(SEL_Z, W2 + l * 128 * 128, b2 + l * 128,
                                    hout[l], FLAG_RELU | FLAG_BIAS, x, out);
    }

    // final: out = concat(x,h1,h2,h3) @ fw + fb  (4 accumulating K=128 passes)
    gemm128_kernel<<<GB, 256>>>(SEL_X,  fw + 0 * 128 * 128, fb,      SEL_OUT, FLAG_BIAS, x, out);
    gemm128_kernel<<<GB, 256>>>(SEL_H0, fw + 1 * 128 * 128, nullptr, SEL_OUT, FLAG_ACC,  x, out);
    gemm128_kernel<<<GB, 256>>>(SEL_H1, fw + 2 * 128 * 128, nullptr, SEL_OUT, FLAG_ACC,  x, out);
    gemm128_kernel<<<GB, 256>>>(SEL_H2, fw + 3 * 128 * 128, nullptr, SEL_OUT, FLAG_ACC,  x, out);
}

// round 3
// speedup vs baseline: 1.1315x; 1.1315x over previous
#include <cuda_runtime.h>

#define N_NODES 50000
#define N_EDGES 640000
#define D 128
#define NBLK 196   // ceil(50000/256)

// ---------------- scratch (device globals; no allocs allowed) ----------------
__device__ float g_h[3][N_NODES * D];   // layer outputs h1,h2,h3
__device__ float g_t[N_NODES * D];      // (1+eps)*h + agg
__device__ float g_z[N_NODES * D];      // mid-MLP
__device__ int   g_rowptr[N_NODES + 1];
__device__ int   g_cnt[N_NODES];
__device__ int   g_srcs[N_EDGES];
__device__ int   g_is64;
__device__ int   g_bsum[256];
__device__ int   g_boff[256];

#define SEL_X   0
#define SEL_T   1
#define SEL_Z   2
#define SEL_H0  3
#define SEL_H1  4
#define SEL_H2  5

__device__ __forceinline__ float* sel_buf(int sel, const float* x) {
    switch (sel) {
        case SEL_X:  return (float*)x;
        case SEL_T:  return g_t;
        case SEL_Z:  return g_z;
        case SEL_H0: return g_h[0];
        case SEL_H1: return g_h[1];
        default:     return g_h[2];
    }
}

// ---------------- edge dtype detection ----------------
__global__ void detect_kernel(const int* __restrict__ ei32) {
    if (threadIdx.x == 0 && blockIdx.x == 0) {
        int ornz = 0;
#pragma unroll
        for (int i = 0; i < 64; i++) ornz |= ei32[2 * i + 1];
        g_is64 = (ornz == 0) ? 1 : 0;
    }
}

__device__ __forceinline__ int edge_val(const int* ei32, int is64, long long idx) {
    return is64 ? ei32[2 * idx] : ei32[idx];
}

// ---------------- CSR build ----------------
__global__ void zero_cnt_kernel() {
    int i = blockIdx.x * blockDim.x + threadIdx.x;
    if (i < N_NODES) g_cnt[i] = 0;
}

__global__ void hist_kernel(const int* __restrict__ ei32) {
    int e = blockIdx.x * blockDim.x + threadIdx.x;
    if (e < N_EDGES) {
        int is64 = g_is64;
        int dst = edge_val(ei32, is64, (long long)N_EDGES + e);
        if ((unsigned)dst < (unsigned)N_NODES) atomicAdd(&g_cnt[dst], 1);
    }
}

// phase A: per-block sums of g_cnt
__global__ void bsum_kernel() {
    __shared__ int sh[256];
    int t = threadIdx.x;
    int i = blockIdx.x * 256 + t;
    sh[t] = (i < N_NODES) ? g_cnt[i] : 0;
    __syncthreads();
#pragma unroll
    for (int off = 128; off > 0; off >>= 1) {
        if (t < off) sh[t] += sh[t + off];
        __syncthreads();
    }
    if (t == 0) g_bsum[blockIdx.x] = sh[0];
}

// phase B: exclusive scan of 196 block sums (1 block)
__global__ void bscan_kernel() {
    __shared__ int sh[256];
    int t = threadIdx.x;
    int v = (t < NBLK) ? g_bsum[t] : 0;
    sh[t] = v;
    __syncthreads();
#pragma unroll
    for (int off = 1; off < 256; off <<= 1) {
        int a = (t >= off) ? sh[t - off] : 0;
        __syncthreads();
        sh[t] += a;
        __syncthreads();
    }
    g_boff[t] = sh[t] - v;
    if (t == 255) g_rowptr[N_NODES] = sh[255];
}

// phase C: per-block exclusive scan + offset -> rowptr
__global__ void rowptr_kernel() {
    __shared__ int sh[256];
    int t = threadIdx.x;
    int i = blockIdx.x * 256 + t;
    int v = (i < N_NODES) ? g_cnt[i] : 0;
    sh[t] = v;
    __syncthreads();
#pragma unroll
    for (int off = 1; off < 256; off <<= 1) {
        int a = (t >= off) ? sh[t - off] : 0;
        __syncthreads();
        sh[t] += a;
        __syncthreads();
    }
    if (i < N_NODES) g_rowptr[i] = g_boff[blockIdx.x] + sh[t] - v;
}

__global__ void scatter_kernel(const int* __restrict__ ei32) {
    int e = blockIdx.x * blockDim.x + threadIdx.x;
    if (e < N_EDGES) {
        int is64 = g_is64;
        int src = edge_val(ei32, is64, e);
        int dst = edge_val(ei32, is64, (long long)N_EDGES + e);
        if ((unsigned)dst < (unsigned)N_NODES && (unsigned)src < (unsigned)N_NODES) {
            int pos = g_rowptr[dst] + atomicAdd(&g_cnt[dst], 1);
            if ((unsigned)pos < (unsigned)N_EDGES) g_srcs[pos] = src;
        }
    }
}

// ---------------- aggregation: t = (1+eps[l])*h + segment_sum(h[src]) --------
__global__ void agg_kernel(int hin_sel, const float* __restrict__ x,
                           const float* __restrict__ eps, int l) {
    const float* h = sel_buf(hin_sel, x);
    int w = (blockIdx.x * blockDim.x + threadIdx.x) >> 5;
    int lane = threadIdx.x & 31;
    if (w >= N_NODES) return;
    int beg = g_rowptr[w], end = g_rowptr[w + 1];
    const float4* hp = (const float4*)h;
    float4 acc = make_float4(0.f, 0.f, 0.f, 0.f);
    for (int i = beg; i < end; i++) {
        int s = g_srcs[i];
        float4 v = __ldg(&hp[s * 32 + lane]);
        acc.x += v.x; acc.y += v.y; acc.z += v.z; acc.w += v.w;
    }
    float e = 1.0f + eps[l];
    float4 hv = hp[w * 32 + lane];
    float4 o = make_float4(fmaf(e, hv.x, acc.x), fmaf(e, hv.y, acc.y),
                           fmaf(e, hv.z, acc.z), fmaf(e, hv.w, acc.w));
    ((float4*)g_t)[w * 32 + lane] = o;
}

// ---------------- FFMA2 helpers ----------------
__device__ __forceinline__ unsigned long long ffma2(unsigned long long a,
                                                    unsigned long long b,
                                                    unsigned long long c) {
    asm("fma.rn.f32x2 %0, %1, %2, %0;" : "+l"(c) : "l"(a), "l"(b));
    return c;
}

__device__ __forceinline__ unsigned long long dup2(float a) {
    unsigned int au = __float_as_uint(a);
    unsigned long long ad;
    asm("mov.b64 %0, {%1, %2};" : "=l"(ad) : "r"(au), "r"(au));
    return ad;
}

// inner product update over a BK=32 smem tile (k-paired A loads)
__device__ __forceinline__ void mma_tile(const float As[128][36],
                                         const float Ws[32][128],
                                         unsigned long long acc[8][4],
                                         int ty, int tx) {
#pragma unroll
    for (int k = 0; k < 32; k += 2) {
        float2 av[8];
#pragma unroll
        for (int i = 0; i < 8; i++)
            av[i] = *(const float2*)&As[(ty << 3) + i][k];
#pragma unroll
        for (int kk = 0; kk < 2; kk++) {
            unsigned long long bp[4];
            {
                const ulonglong2* wp = (const ulonglong2*)&Ws[k + kk][tx << 3];
                ulonglong2 b0 = wp[0];
                ulonglong2 b1 = wp[1];
                bp[0] = b0.x; bp[1] = b0.y; bp[2] = b1.x; bp[3] = b1.y;
            }
#pragma unroll
            for (int i = 0; i < 8; i++) {
                unsigned long long ad = dup2(kk ? av[i].y : av[i].x);
#pragma unroll
                for (int j = 0; j < 4; j++) acc[i][j] = ffma2(ad, bp[j], acc[i][j]);
            }
        }
    }
}

// ---------------- layer GEMM: out = [relu]( A[M,128] @ W[128,128] + bias ) ---
#define FLAG_RELU 1

__global__ void __launch_bounds__(256, 2)
gemm128_kernel(int a_sel, const float* __restrict__ W,
               const float* __restrict__ bias, int o_sel, int flags,
               const float* __restrict__ x) {
    __shared__ float As[128][36];
    __shared__ float Ws[32][128];

    const float* A = sel_buf(a_sel, x);
    float* out = sel_buf(o_sel, x);

    const int tid = threadIdx.x;
    const int tx = tid & 15;
    const int ty = tid >> 4;
    const int rowBase = blockIdx.x * 128;
    const int M = N_NODES;

    unsigned long long acc[8][4];
#pragma unroll
    for (int i = 0; i < 8; i++)
#pragma unroll
        for (int j = 0; j < 4; j++) acc[i][j] = 0ULL;

    const int ar  = tid >> 3;
    const int ac4 = (tid & 7) << 2;
    const int wr  = tid >> 5;
    const int wc4 = (tid & 31) << 2;

    for (int kc = 0; kc < 128; kc += 32) {
#pragma unroll
        for (int rr = 0; rr < 128; rr += 32) {
            int row = rowBase + rr + ar;
            float4 v = make_float4(0.f, 0.f, 0.f, 0.f);
            if (row < M) v = *(const float4*)&A[row * 128 + kc + ac4];
            *(float4*)&As[rr + ar][ac4] = v;
        }
#pragma unroll
        for (int rr = 0; rr < 32; rr += 8)
            *(float4*)&Ws[rr + wr][wc4] =
                *(const float4*)&W[(kc + rr + wr) * 128 + wc4];
        __syncthreads();

        mma_tile(As, Ws, acc, ty, tx);
        __syncthreads();
    }

    const bool relu = (flags & FLAG_RELU) != 0;
    float bvals[8];
#pragma unroll
    for (int j = 0; j < 8; j++) bvals[j] = bias[(tx << 3) + j];

#pragma unroll
    for (int i = 0; i < 8; i++) {
        int row = rowBase + (ty << 3) + i;
        if (row < M) {
            float o[8];
#pragma unroll
            for (int j = 0; j < 4; j++) {
                float2 p = *(float2*)&acc[i][j];
                o[2 * j] = p.x; o[2 * j + 1] = p.y;
            }
#pragma unroll
            for (int j = 0; j < 8; j++) {
                o[j] += bvals[j];
                if (relu) o[j] = fmaxf(o[j], 0.f);
            }
            float* op = &out[row * 128 + (tx << 3)];
            *(float4*)&op[0] = make_float4(o[0], o[1], o[2], o[3]);
            *(float4*)&op[4] = make_float4(o[4], o[5], o[6], o[7]);
        }
    }
}

// ---------------- final GEMM: out = concat(x,h0,h1,h2) @ fw + fb (K=512) -----
__global__ void __launch_bounds__(256, 2)
final_gemm_kernel(const float* __restrict__ fw, const float* __restrict__ fb,
                  const float* __restrict__ x, float* __restrict__ out) {
    __shared__ float As[128][36];
    __shared__ float Ws[32][128];

    const int tid = threadIdx.x;
    const int tx = tid & 15;
    const int ty = tid >> 4;
    const int rowBase = blockIdx.x * 128;
    const int M = N_NODES;

    unsigned long long acc[8][4];
#pragma unroll
    for (int i = 0; i < 8; i++)
#pragma unroll
        for (int j = 0; j < 4; j++) acc[i][j] = 0ULL;

    const int ar  = tid >> 3;
    const int ac4 = (tid & 7) << 2;
    const int wr  = tid >> 5;
    const int wc4 = (tid & 31) << 2;

    for (int kc = 0; kc < 512; kc += 32) {
        const float* A;
        switch (kc >> 7) {
            case 0:  A = x;      break;
            case 1:  A = g_h[0]; break;
            case 2:  A = g_h[1]; break;
            default: A = g_h[2]; break;
        }
        const int kl = kc & 127;
#pragma unroll
        for (int rr = 0; rr < 128; rr += 32) {
            int row = rowBase + rr + ar;
            float4 v = make_float4(0.f, 0.f, 0.f, 0.f);
            if (row < M) v = *(const float4*)&A[row * 128 + kl + ac4];
            *(float4*)&As[rr + ar][ac4] = v;
        }
#pragma unroll
        for (int rr = 0; rr < 32; rr += 8)
            *(float4*)&Ws[rr + wr][wc4] =
                *(const float4*)&fw[(kc + rr + wr) * 128 + wc4];
        __syncthreads();

        mma_tile(As, Ws, acc, ty, tx);
        __syncthreads();
    }

    float bvals[8];
#pragma unroll
    for (int j = 0; j < 8; j++) bvals[j] = fb[(tx << 3) + j];

#pragma unroll
    for (int i = 0; i < 8; i++) {
        int row = rowBase + (ty << 3) + i;
        if (row < M) {
            float o[8];
#pragma unroll
            for (int j = 0; j < 4; j++) {
                float2 p = *(float2*)&acc[i][j];
                o[2 * j] = p.x; o[2 * j + 1] = p.y;
            }
#pragma unroll
            for (int j = 0; j < 8; j++) o[j] += bvals[j];
            float* op = &out[row * 128 + (tx << 3)];
            *(float4*)&op[0] = make_float4(o[0], o[1], o[2], o[3]);
            *(float4*)&op[4] = make_float4(o[4], o[5], o[6], o[7]);
        }
    }
}

// ---------------- launch ----------------
extern "C" void kernel_launch(void* const* d_in, const int* in_sizes, int n_in,
                              void* d_out, int out_size) {
    const float* x   = (const float*)d_in[0];
    const int*   ei  = (const int*)d_in[1];
    const float* W1  = (const float*)d_in[2];
    const float* b1  = (const float*)d_in[3];
    const float* W2  = (const float*)d_in[4];
    const float* b2  = (const float*)d_in[5];
    const float* eps = (const float*)d_in[6];
    const float* fw  = (const float*)d_in[7];
    const float* fb  = (const float*)d_in[8];
    float* out = (float*)d_out;

    const int EB = (N_EDGES + 255) / 256;
    const int GB = (N_NODES + 127) / 128;
    const int AB = (N_NODES * 32 + 255) / 256;

    // CSR build
    detect_kernel<<<1, 32>>>(ei);
    zero_cnt_kernel<<<NBLK, 256>>>();
    hist_kernel<<<EB, 256>>>(ei);
    bsum_kernel<<<NBLK, 256>>>();
    bscan_kernel<<<1, 256>>>();
    rowptr_kernel<<<NBLK, 256>>>();
    zero_cnt_kernel<<<NBLK, 256>>>();
    scatter_kernel<<<EB, 256>>>(ei);

    // 3 GIN layers
    int hin[3]  = { SEL_X, SEL_H0, SEL_H1 };
    int hout[3] = { SEL_H0, SEL_H1, SEL_H2 };
    for (int l = 0; l < 3; l++) {
        agg_kernel<<<AB, 256>>>(hin[l], x, eps, l);
        gemm128_kernel<<<GB, 256>>>(SEL_T, W1 + l * 128 * 128, b1 + l * 128,
                                    SEL_Z, FLAG_RELU, x);
        gemm128_kernel<<<GB, 256>>>(SEL_Z, W2 + l * 128 * 128, b2 + l * 128,
                                    hout[l], FLAG_RELU, x);
    }

    // final fused K=512 GEMM
    final_gemm_kernel<<<GB, 256>>>(fw, fb, x, out);
}

// round 4
// speedup vs baseline: 1.2123x; 1.0714x over previous
#include <cuda_runtime.h>

#define N_NODES 50000
#define N_EDGES 640000
#define NBLK 196   // ceil(50000/256)

// ---------------- scratch ----------------
__device__ float g_h[3][N_NODES * 128];
__device__ float g_t[N_NODES * 128];
__device__ float g_z[N_NODES * 128];
__device__ int   g_rowptr[N_NODES + 1];
__device__ int   g_cnt[N_NODES];
__device__ int   g_cnt2[N_NODES];
__device__ int   g_srcs[N_EDGES];
__device__ int   g_is64;
__device__ int   g_bsum[256];
__device__ int   g_boff[256];

#define SEL_X   0
#define SEL_T   1
#define SEL_Z   2
#define SEL_H0  3
#define SEL_H1  4
#define SEL_H2  5

__device__ __forceinline__ float* sel_buf(int sel, const float* x) {
    switch (sel) {
        case SEL_X:  return (float*)x;
        case SEL_T:  return g_t;
        case SEL_Z:  return g_z;
        case SEL_H0: return g_h[0];
        case SEL_H1: return g_h[1];
        default:     return g_h[2];
    }
}

// ---------------- CSR build ----------------
__global__ void detect_zero_kernel(const int* __restrict__ ei32) {
    int i = blockIdx.x * 256 + threadIdx.x;
    if (i < N_NODES) g_cnt[i] = 0;
    if (blockIdx.x == 0 && threadIdx.x == 0) {
        int ornz = 0;
#pragma unroll
        for (int k = 0; k < 64; k++) ornz |= ei32[2 * k + 1];
        g_is64 = (ornz == 0) ? 1 : 0;
    }
}

__device__ __forceinline__ int edge_val(const int* ei32, int is64, long long idx) {
    return is64 ? ei32[2 * idx] : ei32[idx];
}

__global__ void hist_kernel(const int* __restrict__ ei32) {
    int e = blockIdx.x * blockDim.x + threadIdx.x;
    if (e < N_EDGES) {
        int dst = edge_val(ei32, g_is64, (long long)N_EDGES + e);
        if ((unsigned)dst < (unsigned)N_NODES) atomicAdd(&g_cnt[dst], 1);
    }
}

__global__ void bsum_kernel() {   // also zeroes g_cnt2
    __shared__ int sh[256];
    int t = threadIdx.x;
    int i = blockIdx.x * 256 + t;
    if (i < N_NODES) g_cnt2[i] = 0;
    sh[t] = (i < N_NODES) ? g_cnt[i] : 0;
    __syncthreads();
#pragma unroll
    for (int off = 128; off > 0; off >>= 1) {
        if (t < off) sh[t] += sh[t + off];
        __syncthreads();
    }
    if (t == 0) g_bsum[blockIdx.x] = sh[0];
}

__global__ void bscan_kernel() {
    __shared__ int sh[256];
    int t = threadIdx.x;
    int v = (t < NBLK) ? g_bsum[t] : 0;
    sh[t] = v;
    __syncthreads();
#pragma unroll
    for (int off = 1; off < 256; off <<= 1) {
        int a = (t >= off) ? sh[t - off] : 0;
        __syncthreads();
        sh[t] += a;
        __syncthreads();
    }
    g_boff[t] = sh[t] - v;
    if (t == 255) g_rowptr[N_NODES] = sh[255];
}

__global__ void rowptr_kernel() {
    __shared__ int sh[256];
    int t = threadIdx.x;
    int i = blockIdx.x * 256 + t;
    int v = (i < N_NODES) ? g_cnt[i] : 0;
    sh[t] = v;
    __syncthreads();
#pragma unroll
    for (int off = 1; off < 256; off <<= 1) {
        int a = (t >= off) ? sh[t - off] : 0;
        __syncthreads();
        sh[t] += a;
        __syncthreads();
    }
    if (i < N_NODES) g_rowptr[i] = g_boff[blockIdx.x] + sh[t] - v;
}

__global__ void scatter_kernel(const int* __restrict__ ei32) {
    int e = blockIdx.x * blockDim.x + threadIdx.x;
    if (e < N_EDGES) {
        int is64 = g_is64;
        int src = edge_val(ei32, is64, e);
        int dst = edge_val(ei32, is64, (long long)N_EDGES + e);
        if ((unsigned)dst < (unsigned)N_NODES && (unsigned)src < (unsigned)N_NODES) {
            int pos = g_rowptr[dst] + atomicAdd(&g_cnt2[dst], 1);
            if ((unsigned)pos < (unsigned)N_EDGES) g_srcs[pos] = src;
        }
    }
}

// ---------------- aggregation (unroll-4, MLP=4) ----------------
__global__ void agg_kernel(int hin_sel, const float* __restrict__ x,
                           const float* __restrict__ eps, int l) {
    const float* h = sel_buf(hin_sel, x);
    int w = (blockIdx.x * blockDim.x + threadIdx.x) >> 5;
    int lane = threadIdx.x & 31;
    if (w >= N_NODES) return;
    int beg = g_rowptr[w], end = g_rowptr[w + 1];
    const float4* hp = (const float4*)h;
    float4 a0 = make_float4(0.f, 0.f, 0.f, 0.f), a1 = a0, a2 = a0, a3 = a0;
    int i = beg;
    for (; i + 4 <= end; i += 4) {
        int s0 = g_srcs[i], s1 = g_srcs[i + 1], s2 = g_srcs[i + 2], s3 = g_srcs[i + 3];
        float4 v0 = __ldg(&hp[s0 * 32 + lane]);
        float4 v1 = __ldg(&hp[s1 * 32 + lane]);
        float4 v2 = __ldg(&hp[s2 * 32 + lane]);
        float4 v3 = __ldg(&hp[s3 * 32 + lane]);
        a0.x += v0.x; a0.y += v0.y; a0.z += v0.z; a0.w += v0.w;
        a1.x += v1.x; a1.y += v1.y; a1.z += v1.z; a1.w += v1.w;
        a2.x += v2.x; a2.y += v2.y; a2.z += v2.z; a2.w += v2.w;
        a3.x += v3.x; a3.y += v3.y; a3.z += v3.z; a3.w += v3.w;
    }
    for (; i < end; i++) {
        float4 v = __ldg(&hp[g_srcs[i] * 32 + lane]);
        a0.x += v.x; a0.y += v.y; a0.z += v.z; a0.w += v.w;
    }
    a0.x += a1.x + a2.x + a3.x; a0.y += a1.y + a2.y + a3.y;
    a0.z += a1.z + a2.z + a3.z; a0.w += a1.w + a2.w + a3.w;
    float e = 1.0f + eps[l];
    float4 hv = hp[w * 32 + lane];
    ((float4*)g_t)[w * 32 + lane] =
        make_float4(fmaf(e, hv.x, a0.x), fmaf(e, hv.y, a0.y),
                    fmaf(e, hv.z, a0.z), fmaf(e, hv.w, a0.w));
}

// ---------------- GEMM machinery ----------------
#define FLAG_RELU 1
#define BM 64
#define BK 16

__device__ __forceinline__ unsigned long long ffma2(unsigned long long a,
                                                    unsigned long long b,
                                                    unsigned long long c) {
    asm("fma.rn.f32x2 %0, %1, %2, %0;" : "+l"(c) : "l"(a), "l"(b));
    return c;
}
__device__ __forceinline__ unsigned long long dup2(float a) {
    unsigned int au = __float_as_uint(a);
    unsigned long long ad;
    asm("mov.b64 %0, {%1, %2};" : "=l"(ad) : "r"(au), "r"(au));
    return ad;
}
__device__ __forceinline__ void cp16(unsigned s, const void* g, bool pred) {
    int sz = pred ? 16 : 0;
    asm volatile("cp.async.cg.shared.global [%0], [%1], 16, %2;\n"
                 :: "r"(s), "l"(g), "r"(sz));
}
__device__ __forceinline__ void cp_commit() { asm volatile("cp.async.commit_group;\n"); }
__device__ __forceinline__ void cp_wait0()  { asm volatile("cp.async.wait_group 0;\n" ::: "memory"); }

// shared tiles: As[2][64][20] (pad 20 keeps 16B-aligned rows), Ws[2][16][128]
// load one BK=16 chunk into buffer b
__device__ __forceinline__ void load_chunk(unsigned sA, unsigned sW,
                                           const float* __restrict__ Asrc, int kl,
                                           const float* __restrict__ Wsrc, int kw,
                                           int rowBase, int tid) {
    int r  = tid >> 2;            // 0..63
    int c4 = (tid & 3) << 2;      // 0,4,8,12
    int row = rowBase + r;
    cp16(sA + (unsigned)((r * 20 + c4) * 4),
         &Asrc[(long long)row * 128 + kl + c4], row < N_NODES);
#pragma unroll
    for (int p = 0; p < 2; p++) {
        int idx = tid + 256 * p;
        int wr = idx >> 5;            // 0..15
        int wc = (idx & 31) << 2;     // 0..124
        cp16(sW + (unsigned)((wr * 128 + wc) * 4),
             &Wsrc[(long long)(kw + wr) * 128 + wc], true);
    }
}

// compute one BK=16 chunk; cols per thread: {4tx..+3} and {64+4tx..+3}
__device__ __forceinline__ void mma_chunk(const float* As, const float* Ws,
                                          unsigned long long acc[4][4],
                                          int ty, int tx) {
#pragma unroll
    for (int k = 0; k < BK; k += 2) {
        float2 av[4];
#pragma unroll
        for (int i = 0; i < 4; i++)
            av[i] = *(const float2*)&As[(ty * 4 + i) * 20 + k];
#pragma unroll
        for (int kk = 0; kk < 2; kk++) {
            unsigned long long bp[4];
            {
                const ulonglong2* w0 = (const ulonglong2*)&Ws[(k + kk) * 128 + 4 * tx];
                const ulonglong2* w1 = (const ulonglong2*)&Ws[(k + kk) * 128 + 64 + 4 * tx];
                ulonglong2 b0 = *w0, b1 = *w1;
                bp[0] = b0.x; bp[1] = b0.y; bp[2] = b1.x; bp[3] = b1.y;
            }
#pragma unroll
            for (int i = 0; i < 4; i++) {
                unsigned long long ad = dup2(kk ? av[i].y : av[i].x);
#pragma unroll
                for (int j = 0; j < 4; j++) acc[i][j] = ffma2(ad, bp[j], acc[i][j]);
            }
        }
    }
}

__device__ __forceinline__ void epilogue(unsigned long long acc[4][4], float* out,
                                         const float* bias, int rowBase,
                                         int ty, int tx, bool relu) {
    float bv[8];
#pragma unroll
    for (int j = 0; j < 4; j++) { bv[j] = bias[4 * tx + j]; bv[4 + j] = bias[64 + 4 * tx + j]; }
#pragma unroll
    for (int i = 0; i < 4; i++) {
        int row = rowBase + ty * 4 + i;
        if (row < N_NODES) {
            float o[8];
#pragma unroll
            for (int j = 0; j < 4; j++) {
                float2 p = *(float2*)&acc[i][j];
                o[2 * j] = p.x; o[2 * j + 1] = p.y;
            }
#pragma unroll
            for (int j = 0; j < 8; j++) {
                o[j] += bv[j];
                if (relu) o[j] = fmaxf(o[j], 0.f);
            }
            float* op = &out[(long long)row * 128];
            *(float4*)&op[4 * tx]      = make_float4(o[0], o[1], o[2], o[3]);
            *(float4*)&op[64 + 4 * tx] = make_float4(o[4], o[5], o[6], o[7]);
        }
    }
}

// ---------------- layer GEMM (K=128, 8 chunks) ----------------
__global__ void __launch_bounds__(256, 2)
gemm128_kernel(int a_sel, const float* __restrict__ W,
               const float* __restrict__ bias, int o_sel, int flags,
               const float* __restrict__ x) {
    __shared__ float As[2][BM * 20];
    __shared__ float Ws[2][BK * 128];
    const float* A = sel_buf(a_sel, x);
    float* out = sel_buf(o_sel, x);

    const int tid = threadIdx.x;
    const int tx = tid & 15, ty = tid >> 4;
    const int rowBase = blockIdx.x * BM;
    unsigned sA[2], sW[2];
#pragma unroll
    for (int b = 0; b < 2; b++) {
        sA[b] = (unsigned)__cvta_generic_to_shared(As[b]);
        sW[b] = (unsigned)__cvta_generic_to_shared(Ws[b]);
    }

    unsigned long long acc[4][4];
#pragma unroll
    for (int i = 0; i < 4; i++)
#pragma unroll
        for (int j = 0; j < 4; j++) acc[i][j] = 0ULL;

    load_chunk(sA[0], sW[0], A, 0, W, 0, rowBase, tid);
    cp_commit(); cp_wait0(); __syncthreads();

#pragma unroll
    for (int c = 0; c < 8; c++) {
        if (c + 1 < 8) {
            load_chunk(sA[(c + 1) & 1], sW[(c + 1) & 1], A, (c + 1) * BK,
                       W, (c + 1) * BK, rowBase, tid);
            cp_commit();
        }
        mma_chunk(As[c & 1], Ws[c & 1], acc, ty, tx);
        cp_wait0();
        __syncthreads();
    }
    epilogue(acc, out, bias, rowBase, ty, tx, (flags & FLAG_RELU) != 0);
}

// ---------------- final GEMM (K=512 over 4 sources, 32 chunks) ----------------
__global__ void __launch_bounds__(256, 2)
final_gemm_kernel(const float* __restrict__ fw, const float* __restrict__ fb,
                  const float* __restrict__ x, float* __restrict__ out) {
    __shared__ float As[2][BM * 20];
    __shared__ float Ws[2][BK * 128];

    const int tid = threadIdx.x;
    const int tx = tid & 15, ty = tid >> 4;
    const int rowBase = blockIdx.x * BM;
    unsigned sA[2], sW[2];
#pragma unroll
    for (int b = 0; b < 2; b++) {
        sA[b] = (unsigned)__cvta_generic_to_shared(As[b]);
        sW[b] = (unsigned)__cvta_generic_to_shared(Ws[b]);
    }

    unsigned long long acc[4][4];
#pragma unroll
    for (int i = 0; i < 4; i++)
#pragma unroll
        for (int j = 0; j < 4; j++) acc[i][j] = 0ULL;

    const float* srcs[4] = { x, g_h[0], g_h[1], g_h[2] };

    load_chunk(sA[0], sW[0], srcs[0], 0, fw, 0, rowBase, tid);
    cp_commit(); cp_wait0(); __syncthreads();

    for (int c = 0; c < 32; c++) {
        if (c + 1 < 32) {
            int cn = c + 1;
            load_chunk(sA[cn & 1], sW[cn & 1], srcs[cn >> 3], (cn & 7) * BK,
                       fw, cn * BK, rowBase, tid);
            cp_commit();
        }
        mma_chunk(As[c & 1], Ws[c & 1], acc, ty, tx);
        cp_wait0();
        __syncthreads();
    }
    epilogue(acc, out, fb, rowBase, ty, tx, false);
}

// ---------------- launch ----------------
extern "C" void kernel_launch(void* const* d_in, const int* in_sizes, int n_in,
                              void* d_out, int out_size) {
    const float* x   = (const float*)d_in[0];
    const int*   ei  = (const int*)d_in[1];
    const float* W1  = (const float*)d_in[2];
    const float* b1  = (const float*)d_in[3];
    const float* W2  = (const float*)d_in[4];
    const float* b2  = (const float*)d_in[5];
    const float* eps = (const float*)d_in[6];
    const float* fw  = (const float*)d_in[7];
    const float* fb  = (const float*)d_in[8];
    float* out = (float*)d_out;

    const int EB = (N_EDGES + 255) / 256;
    const int GB = (N_NODES + BM - 1) / BM;      // 782
    const int AB = (N_NODES * 32 + 255) / 256;

    detect_zero_kernel<<<NBLK, 256>>>(ei);
    hist_kernel<<<EB, 256>>>(ei);
    bsum_kernel<<<NBLK, 256>>>();
    bscan_kernel<<<1, 256>>>();
    rowptr_kernel<<<NBLK, 256>>>();
    scatter_kernel<<<EB, 256>>>(ei);

    int hin[3]  = { SEL_X, SEL_H0, SEL_H1 };
    int hout[3] = { SEL_H0, SEL_H1, SEL_H2 };
    for (int l = 0; l < 3; l++) {
        agg_kernel<<<AB, 256>>>(hin[l], x, eps, l);
        gemm128_kernel<<<GB, 256>>>(SEL_T, W1 + l * 128 * 128, b1 + l * 128,
                                    SEL_Z, FLAG_RELU, x);
        gemm128_kernel<<<GB, 256>>>(SEL_Z, W2 + l * 128 * 128, b2 + l * 128,
                                    hout[l], FLAG_RELU, x);
    }
    final_gemm_kernel<<<GB, 256>>>(fw, fb, x, out);
}

// round 5
// speedup vs baseline: 1.6551x; 1.3653x over previous
#include <cuda_runtime.h>
#include <cuda_bf16.h>

#define N_NODES 50000
#define N_EDGES 640000
#define NELEM (N_NODES * 128)
#define NBLK 196

// ---------------- scratch (device globals) ----------------
__device__ __align__(16) __nv_bfloat16 g_xhi[NELEM], g_xlo[NELEM];
__device__ __align__(16) __nv_bfloat16 g_thi[NELEM], g_tlo[NELEM];
__device__ __align__(16) __nv_bfloat16 g_zhi[NELEM], g_zlo[NELEM];
__device__ __align__(16) __nv_bfloat16 g_hhi[3][NELEM], g_hlo[3][NELEM];
__device__ __align__(16) __nv_bfloat16 g_wthi[6][128 * 128], g_wtlo[6][128 * 128];
__device__ __align__(16) __nv_bfloat16 g_fwthi[128 * 512], g_fwtlo[128 * 512];
__device__ int g_rowptr[N_NODES + 1], g_cnt[N_NODES], g_cnt2[N_NODES], g_srcs[N_EDGES];
__device__ int g_is64, g_bsum[256], g_boff[256];

#define SEL_X 0
#define SEL_T 1
#define SEL_Z 2
#define SEL_H0 3
#define SEL_H1 4
#define SEL_H2 5

__device__ __forceinline__ void sel_hl(int s, const __nv_bfloat16*& hi,
                                       const __nv_bfloat16*& lo) {
    switch (s) {
        case SEL_X: hi = g_xhi; lo = g_xlo; break;
        case SEL_T: hi = g_thi; lo = g_tlo; break;
        case SEL_Z: hi = g_zhi; lo = g_zlo; break;
        case SEL_H0: hi = g_hhi[0]; lo = g_hlo[0]; break;
        case SEL_H1: hi = g_hhi[1]; lo = g_hlo[1]; break;
        default:     hi = g_hhi[2]; lo = g_hlo[2]; break;
    }
}
__device__ __forceinline__ void sel_out(int s, __nv_bfloat16*& hi, __nv_bfloat16*& lo) {
    switch (s) {
        case SEL_T: hi = g_thi; lo = g_tlo; break;
        case SEL_Z: hi = g_zhi; lo = g_zlo; break;
        case SEL_H0: hi = g_hhi[0]; lo = g_hlo[0]; break;
        case SEL_H1: hi = g_hhi[1]; lo = g_hlo[1]; break;
        default:     hi = g_hhi[2]; lo = g_hlo[2]; break;
    }
}

// ---------------- CSR build ----------------
__global__ void detect_zero_kernel(const int* __restrict__ ei32) {
    int i = blockIdx.x * 256 + threadIdx.x;
    if (i < N_NODES) g_cnt[i] = 0;
    if (blockIdx.x == 0 && threadIdx.x == 0) {
        int ornz = 0;
#pragma unroll
        for (int k = 0; k < 64; k++) ornz |= ei32[2 * k + 1];
        g_is64 = (ornz == 0) ? 1 : 0;
    }
}
__device__ __forceinline__ int edge_val(const int* ei32, int is64, long long idx) {
    return is64 ? ei32[2 * idx] : ei32[idx];
}
__global__ void hist_kernel(const int* __restrict__ ei32) {
    int e = blockIdx.x * blockDim.x + threadIdx.x;
    if (e < N_EDGES) {
        int dst = edge_val(ei32, g_is64, (long long)N_EDGES + e);
        if ((unsigned)dst < (unsigned)N_NODES) atomicAdd(&g_cnt[dst], 1);
    }
}
__global__ void bsum_kernel() {
    __shared__ int sh[256];
    int t = threadIdx.x, i = blockIdx.x * 256 + t;
    if (i < N_NODES) g_cnt2[i] = 0;
    sh[t] = (i < N_NODES) ? g_cnt[i] : 0;
    __syncthreads();
#pragma unroll
    for (int off = 128; off > 0; off >>= 1) {
        if (t < off) sh[t] += sh[t + off];
        __syncthreads();
    }
    if (t == 0) g_bsum[blockIdx.x] = sh[0];
}
__global__ void bscan_kernel() {
    __shared__ int sh[256];
    int t = threadIdx.x;
    int v = (t < NBLK) ? g_bsum[t] : 0;
    sh[t] = v;
    __syncthreads();
#pragma unroll
    for (int off = 1; off < 256; off <<= 1) {
        int a = (t >= off) ? sh[t - off] : 0;
        __syncthreads();
        sh[t] += a;
        __syncthreads();
    }
    g_boff[t] = sh[t] - v;
    if (t == 255) g_rowptr[N_NODES] = sh[255];
}
__global__ void rowptr_kernel() {
    __shared__ int sh[256];
    int t = threadIdx.x, i = blockIdx.x * 256 + t;
    int v = (i < N_NODES) ? g_cnt[i] : 0;
    sh[t] = v;
    __syncthreads();
#pragma unroll
    for (int off = 1; off < 256; off <<= 1) {
        int a = (t >= off) ? sh[t - off] : 0;
        __syncthreads();
        sh[t] += a;
        __syncthreads();
    }
    if (i < N_NODES) g_rowptr[i] = g_boff[blockIdx.x] + sh[t] - v;
}
__global__ void scatter_kernel(const int* __restrict__ ei32) {
    int e = blockIdx.x * blockDim.x + threadIdx.x;
    if (e < N_EDGES) {
        int is64 = g_is64;
        int src = edge_val(ei32, is64, e);
        int dst = edge_val(ei32, is64, (long long)N_EDGES + e);
        if ((unsigned)dst < (unsigned)N_NODES && (unsigned)src < (unsigned)N_NODES) {
            int pos = g_rowptr[dst] + atomicAdd(&g_cnt2[dst], 1);
            if ((unsigned)pos < (unsigned)N_EDGES) g_srcs[pos] = src;
        }
    }
}

// ---------------- x split ----------------
__global__ void split_x_kernel(const float* __restrict__ x) {
    int i = blockIdx.x * 256 + threadIdx.x;   // 8 floats per thread
    if (i >= NELEM / 8) return;
    const float4* xp = (const float4*)x;
    float4 v0 = xp[2 * i], v1 = xp[2 * i + 1];
    float v[8] = {v0.x, v0.y, v0.z, v0.w, v1.x, v1.y, v1.z, v1.w};
    uint4 hp, lp;
    __nv_bfloat162* h2 = (__nv_bfloat162*)&hp;
    __nv_bfloat162* l2 = (__nv_bfloat162*)&lp;
#pragma unroll
    for (int j = 0; j < 4; j++) {
        __nv_bfloat16 h0 = __float2bfloat16_rn(v[2 * j]);
        __nv_bfloat16 h1 = __float2bfloat16_rn(v[2 * j + 1]);
        h2[j].x = h0; h2[j].y = h1;
        l2[j].x = __float2bfloat16_rn(v[2 * j] - __bfloat162float(h0));
        l2[j].y = __float2bfloat16_rn(v[2 * j + 1] - __bfloat162float(h1));
    }
    ((uint4*)g_xhi)[i] = hp;
    ((uint4*)g_xlo)[i] = lp;
}

// ---------------- weight transpose + split ----------------
__global__ void wprep_kernel(const float* __restrict__ W1, const float* __restrict__ W2,
                             const float* __restrict__ fw) {
    int e = blockIdx.x * 256 + threadIdx.x;
    if (e < 6 * 16384) {
        int m = e >> 14, t = e & 16383;
        int n = t >> 7, k = t & 127;
        int l = m >> 1;
        const float* src = (m & 1) ? W2 : W1;
        float v = src[l * 16384 + k * 128 + n];
        __nv_bfloat16 h = __float2bfloat16_rn(v);
        g_wthi[m][n * 128 + k] = h;
        g_wtlo[m][n * 128 + k] = __float2bfloat16_rn(v - __bfloat162float(h));
    } else if (e < 6 * 16384 + 128 * 512) {
        int t = e - 6 * 16384;
        int n = t >> 9, k = t & 511;
        float v = fw[k * 128 + n];
        __nv_bfloat16 h = __float2bfloat16_rn(v);
        g_fwthi[n * 512 + k] = h;
        g_fwtlo[n * 512 + k] = __float2bfloat16_rn(v - __bfloat162float(h));
    }
}

// ---------------- aggregation: t = (1+eps)*h + segsum (hi/lo pairs) ---------
__global__ void agg_kernel(int hsel, const float* __restrict__ eps, int l) {
    const __nv_bfloat16 *hib, *lob;
    sel_hl(hsel, hib, lob);
    int wnode = (blockIdx.x * blockDim.x + threadIdx.x) >> 5;
    int lane = threadIdx.x & 31;
    if (wnode >= N_NODES) return;
    int half = lane >> 4;            // 0: hi array, 1: lo array
    int p = lane & 15;               // 16B chunk within 256B row
    const uint4* rows = (const uint4*)(half ? lob : hib);   // 16 uint4 per row
    float acc[8];
#pragma unroll
    for (int j = 0; j < 8; j++) acc[j] = 0.f;

    int beg = g_rowptr[wnode], end = g_rowptr[wnode + 1];
    int i = beg;
    for (; i + 2 <= end; i += 2) {
        int s0 = g_srcs[i], s1 = g_srcs[i + 1];
        uint4 v0 = rows[s0 * 16 + p];
        uint4 v1 = rows[s1 * 16 + p];
        const __nv_bfloat162* p0 = (const __nv_bfloat162*)&v0;
        const __nv_bfloat162* p1 = (const __nv_bfloat162*)&v1;
#pragma unroll
        for (int j = 0; j < 4; j++) {
            float2 f0 = __bfloat1622float2(p0[j]);
            float2 f1 = __bfloat1622float2(p1[j]);
            acc[2 * j] += f0.x + f1.x;
            acc[2 * j + 1] += f0.y + f1.y;
        }
    }
    for (; i < end; i++) {
        uint4 v = rows[g_srcs[i] * 16 + p];
        const __nv_bfloat162* pv = (const __nv_bfloat162*)&v;
#pragma unroll
        for (int j = 0; j < 4; j++) {
            float2 f = __bfloat1622float2(pv[j]);
            acc[2 * j] += f.x;
            acc[2 * j + 1] += f.y;
        }
    }
    // self term (this half's contribution; combines to (1+eps)*(hi+lo))
    float e = 1.0f + eps[l];
    {
        uint4 v = rows[wnode * 16 + p];
        const __nv_bfloat162* pv = (const __nv_bfloat162*)&v;
#pragma unroll
        for (int j = 0; j < 4; j++) {
            float2 f = __bfloat1622float2(pv[j]);
            acc[2 * j] += e * f.x;
            acc[2 * j + 1] += e * f.y;
        }
    }
    // combine halves
    float tot[8];
#pragma unroll
    for (int j = 0; j < 8; j++)
        tot[j] = acc[j] + __shfl_xor_sync(0xffffffffu, acc[j], 16);
    // split & store
    uint4 outv;
    __nv_bfloat162* o2 = (__nv_bfloat162*)&outv;
#pragma unroll
    for (int j = 0; j < 4; j++) {
        __nv_bfloat16 h0 = __float2bfloat16_rn(tot[2 * j]);
        __nv_bfloat16 h1 = __float2bfloat16_rn(tot[2 * j + 1]);
        if (half == 0) { o2[j].x = h0; o2[j].y = h1; }
        else {
            o2[j].x = __float2bfloat16_rn(tot[2 * j] - __bfloat162float(h0));
            o2[j].y = __float2bfloat16_rn(tot[2 * j + 1] - __bfloat162float(h1));
        }
    }
    uint4* dst = (uint4*)(half ? g_tlo : g_thi);
    dst[wnode * 16 + p] = outv;
}

// ---------------- tensor-core GEMM machinery ----------------
__device__ __forceinline__ void cp16(unsigned s, const void* g, bool pred) {
    int sz = pred ? 16 : 0;
    asm volatile("cp.async.cg.shared.global [%0], [%1], 16, %2;\n"
                 :: "r"(s), "l"(g), "r"(sz));
}
__device__ __forceinline__ void cp_commit() { asm volatile("cp.async.commit_group;\n"); }
__device__ __forceinline__ void cp_wait0()  { asm volatile("cp.async.wait_group 0;\n" ::: "memory"); }

__device__ __forceinline__ void ldsm4(unsigned* r, unsigned addr) {
    asm volatile("ldmatrix.sync.aligned.m8n8.x4.shared.b16 {%0,%1,%2,%3}, [%4];"
                 : "=r"(r[0]), "=r"(r[1]), "=r"(r[2]), "=r"(r[3]) : "r"(addr));
}
__device__ __forceinline__ void mma_bf16(float* c, const unsigned* a, const unsigned* b) {
    asm volatile(
        "mma.sync.aligned.m16n8k16.row.col.f32.bf16.bf16.f32 "
        "{%0,%1,%2,%3},{%4,%5,%6,%7},{%8,%9},{%0,%1,%2,%3};"
        : "+f"(c[0]), "+f"(c[1]), "+f"(c[2]), "+f"(c[3])
        : "r"(a[0]), "r"(a[1]), "r"(a[2]), "r"(a[3]), "r"(b[0]), "r"(b[1]));
}
__device__ __forceinline__ void store_hl(__nv_bfloat16* Ohi, __nv_bfloat16* Olo,
                                         long long off, float v0, float v1) {
    __nv_bfloat16 h0 = __float2bfloat16_rn(v0), h1 = __float2bfloat16_rn(v1);
    __nv_bfloat162 hp; hp.x = h0; hp.y = h1;
    *(__nv_bfloat162*)(Ohi + off) = hp;
    __nv_bfloat162 lp;
    lp.x = __float2bfloat16_rn(v0 - __bfloat162float(h0));
    lp.y = __float2bfloat16_rn(v1 - __bfloat162float(h1));
    *(__nv_bfloat162*)(Olo + off) = lp;
}

// smem: [stage][mat 0=Ahi 1=Alo 2=Whi 3=Wlo][128 rows * 24 bf16 (48B, pad)]
#define SM_ROW 24

// compute one k16 chunk (all 3 split products)
__device__ __forceinline__ void mma_chunk(const unsigned sb[4], int aoff0, int aoff1,
                                          const int* woff, float acc[2][8][4]) {
    unsigned ah[2][4], al[2][4];
    ldsm4(ah[0], sb[0] + aoff0);
    ldsm4(ah[1], sb[0] + aoff1);
    ldsm4(al[0], sb[1] + aoff0);
    ldsm4(al[1], sb[1] + aoff1);
#pragma unroll
    for (int ng = 0; ng < 4; ng++) {
        unsigned bh[4], bl[4];
        ldsm4(bh, sb[2] + woff[ng]);
        ldsm4(bl, sb[3] + woff[ng]);
#pragma unroll
        for (int mi = 0; mi < 2; mi++)
#pragma unroll
            for (int ns = 0; ns < 2; ns++) {
                float* C = acc[mi][ng * 2 + ns];
                mma_bf16(C, ah[mi], &bh[ns * 2]);
                mma_bf16(C, ah[mi], &bl[ns * 2]);
                mma_bf16(C, al[mi], &bh[ns * 2]);
            }
    }
}

// ---------------- layer GEMM: out = relu(A @ W + bias), K=128 ----------------
__global__ void __launch_bounds__(256, 2)
mma_gemm_kernel(int a_sel, int w_idx, const float* __restrict__ bias, int o_sel) {
    __shared__ __nv_bfloat16 sm[2][4][128 * SM_ROW];
    const __nv_bfloat16 *Ahi, *Alo;
    sel_hl(a_sel, Ahi, Alo);
    __nv_bfloat16 *Ohi, *Olo;
    sel_out(o_sel, Ohi, Olo);
    const __nv_bfloat16* Whi = g_wthi[w_idx];
    const __nv_bfloat16* Wlo = g_wtlo[w_idx];

    const int tid = threadIdx.x, lane = tid & 31, w = tid >> 5;
    const int wm = w & 3, wn = w >> 2;
    const int rowBase = blockIdx.x * 128;
    const int crow = tid >> 1, chalf = tid & 1;
    const int g = lane >> 3, r = lane & 7;

    unsigned sb[2][4];
#pragma unroll
    for (int st = 0; st < 2; st++)
#pragma unroll
        for (int m = 0; m < 4; m++)
            sb[st][m] = (unsigned)__cvta_generic_to_shared(sm[st][m]);

    const int aoff0 = (wm * 32 + 0 + (g & 1) * 8 + r) * 48 + (g >> 1) * 16;
    const int aoff1 = (wm * 32 + 16 + (g & 1) * 8 + r) * 48 + (g >> 1) * 16;
    int woff[4];
#pragma unroll
    for (int ng = 0; ng < 4; ng++)
        woff[ng] = (wn * 64 + ng * 16 + (g >> 1) * 8 + r) * 48 + (g & 1) * 16;

    float acc[2][8][4];
#pragma unroll
    for (int i = 0; i < 2; i++)
#pragma unroll
        for (int j = 0; j < 8; j++)
#pragma unroll
            for (int q = 0; q < 4; q++) acc[i][j][q] = 0.f;

    const unsigned dsto = (unsigned)(crow * 48 + chalf * 16);
    bool aok = (rowBase + crow) < N_NODES;
    const long long arow = (long long)(rowBase + crow) * 128;

    // prologue chunk 0
    cp16(sb[0][0] + dsto, Ahi + arow + chalf * 8, aok);
    cp16(sb[0][1] + dsto, Alo + arow + chalf * 8, aok);
    cp16(sb[0][2] + dsto, Whi + crow * 128 + chalf * 8, true);
    cp16(sb[0][3] + dsto, Wlo + crow * 128 + chalf * 8, true);
    cp_commit(); cp_wait0(); __syncthreads();

#pragma unroll
    for (int c = 0; c < 8; c++) {
        if (c < 7) {
            int kb = (c + 1) * 16 + chalf * 8;
            int st = (c + 1) & 1;
            cp16(sb[st][0] + dsto, Ahi + arow + kb, aok);
            cp16(sb[st][1] + dsto, Alo + arow + kb, aok);
            cp16(sb[st][2] + dsto, Whi + crow * 128 + kb, true);
            cp16(sb[st][3] + dsto, Wlo + crow * 128 + kb, true);
            cp_commit();
        }
        mma_chunk(sb[c & 1], aoff0, aoff1, woff, acc);
        cp_wait0();
        __syncthreads();
    }

    // epilogue: bias + relu, split-store
#pragma unroll
    for (int ni = 0; ni < 8; ni++) {
        int n0 = wn * 64 + ni * 8 + 2 * (lane & 3);
        float2 bv = *(const float2*)&bias[n0];
#pragma unroll
        for (int mi = 0; mi < 2; mi++) {
            int r0 = rowBase + wm * 32 + mi * 16 + (lane >> 2);
            float* C = acc[mi][ni];
            float v0 = fmaxf(C[0] + bv.x, 0.f), v1 = fmaxf(C[1] + bv.y, 0.f);
            float v2 = fmaxf(C[2] + bv.x, 0.f), v3 = fmaxf(C[3] + bv.y, 0.f);
            if (r0 < N_NODES) store_hl(Ohi, Olo, (long long)r0 * 128 + n0, v0, v1);
            if (r0 + 8 < N_NODES) store_hl(Ohi, Olo, (long long)(r0 + 8) * 128 + n0, v2, v3);
        }
    }
}

// ---------------- final GEMM: out = concat(x,h0,h1,h2) @ fw + fb, K=512 ------
__device__ __forceinline__ void final_src(int s, const __nv_bfloat16*& hi,
                                          const __nv_bfloat16*& lo) {
    switch (s) {
        case 0: hi = g_xhi; lo = g_xlo; break;
        case 1: hi = g_hhi[0]; lo = g_hlo[0]; break;
        case 2: hi = g_hhi[1]; lo = g_hlo[1]; break;
        default: hi = g_hhi[2]; lo = g_hlo[2]; break;
    }
}

__global__ void __launch_bounds__(256, 2)
final_gemm_kernel(const float* __restrict__ fb, float* __restrict__ out) {
    __shared__ __nv_bfloat16 sm[2][4][128 * SM_ROW];
    const int tid = threadIdx.x, lane = tid & 31, w = tid >> 5;
    const int wm = w & 3, wn = w >> 2;
    const int rowBase = blockIdx.x * 128;
    const int crow = tid >> 1, chalf = tid & 1;
    const int g = lane >> 3, r = lane & 7;

    unsigned sb[2][4];
#pragma unroll
    for (int st = 0; st < 2; st++)
#pragma unroll
        for (int m = 0; m < 4; m++)
            sb[st][m] = (unsigned)__cvta_generic_to_shared(sm[st][m]);

    const int aoff0 = (wm * 32 + 0 + (g & 1) * 8 + r) * 48 + (g >> 1) * 16;
    const int aoff1 = (wm * 32 + 16 + (g & 1) * 8 + r) * 48 + (g >> 1) * 16;
    int woff[4];
#pragma unroll
    for (int ng = 0; ng < 4; ng++)
        woff[ng] = (wn * 64 + ng * 16 + (g >> 1) * 8 + r) * 48 + (g & 1) * 16;

    float acc[2][8][4];
#pragma unroll
    for (int i = 0; i < 2; i++)
#pragma unroll
        for (int j = 0; j < 8; j++)
#pragma unroll
            for (int q = 0; q < 4; q++) acc[i][j][q] = 0.f;

    const unsigned dsto = (unsigned)(crow * 48 + chalf * 16);
    bool aok = (rowBase + crow) < N_NODES;
    const long long arow = (long long)(rowBase + crow) * 128;

    // prologue chunk 0 (source 0 = x)
    {
        const __nv_bfloat16 *shi, *slo;
        final_src(0, shi, slo);
        cp16(sb[0][0] + dsto, shi + arow + chalf * 8, aok);
        cp16(sb[0][1] + dsto, slo + arow + chalf * 8, aok);
        cp16(sb[0][2] + dsto, g_fwthi + crow * 512 + chalf * 8, true);
        cp16(sb[0][3] + dsto, g_fwtlo + crow * 512 + chalf * 8, true);
        cp_commit(); cp_wait0(); __syncthreads();
    }

    for (int c = 0; c < 32; c++) {
        if (c < 31) {
            int cn = c + 1;
            const __nv_bfloat16 *shi, *slo;
            final_src(cn >> 3, shi, slo);
            int kl = (cn & 7) * 16 + chalf * 8;
            int kw = cn * 16 + chalf * 8;
            int st = cn & 1;
            cp16(sb[st][0] + dsto, shi + arow + kl, aok);
            cp16(sb[st][1] + dsto, slo + arow + kl, aok);
            cp16(sb[st][2] + dsto, g_fwthi + crow * 512 + kw, true);
            cp16(sb[st][3] + dsto, g_fwtlo + crow * 512 + kw, true);
            cp_commit();
        }
        mma_chunk(sb[c & 1], aoff0, aoff1, woff, acc);
        cp_wait0();
        __syncthreads();
    }

#pragma unroll
    for (int ni = 0; ni < 8; ni++) {
        int n0 = wn * 64 + ni * 8 + 2 * (lane & 3);
        float2 bv = *(const float2*)&fb[n0];
#pragma unroll
        for (int mi = 0; mi < 2; mi++) {
            int r0 = rowBase + wm * 32 + mi * 16 + (lane >> 2);
            float* C = acc[mi][ni];
            if (r0 < N_NODES) {
                float2 o = make_float2(C[0] + bv.x, C[1] + bv.y);
                *(float2*)&out[(long long)r0 * 128 + n0] = o;
            }
            if (r0 + 8 < N_NODES) {
                float2 o = make_float2(C[2] + bv.x, C[3] + bv.y);
                *(float2*)&out[(long long)(r0 + 8) * 128 + n0] = o;
            }
        }
    }
}

// ---------------- launch ----------------
extern "C" void kernel_launch(void* const* d_in, const int* in_sizes, int n_in,
                              void* d_out, int out_size) {
    const float* x   = (const float*)d_in[0];
    const int*   ei  = (const int*)d_in[1];
    const float* W1  = (const float*)d_in[2];
    const float* b1  = (const float*)d_in[3];
    const float* W2  = (const float*)d_in[4];
    const float* b2  = (const float*)d_in[5];
    const float* eps = (const float*)d_in[6];
    const float* fw  = (const float*)d_in[7];
    const float* fb  = (const float*)d_in[8];
    float* out = (float*)d_out;

    const int EB = (N_EDGES + 255) / 256;
    const int GB = (N_NODES + 127) / 128;        // 391
    const int AB = (N_NODES * 32 + 255) / 256;   // warp per node

    // CSR build + input prep
    detect_zero_kernel<<<NBLK, 256>>>(ei);
    split_x_kernel<<<(NELEM / 8 + 255) / 256, 256>>>(x);
    wprep_kernel<<<(6 * 16384 + 128 * 512 + 255) / 256, 256>>>(W1, W2, fw);
    hist_kernel<<<EB, 256>>>(ei);
    bsum_kernel<<<NBLK, 256>>>();
    bscan_kernel<<<1, 256>>>();
    rowptr_kernel<<<NBLK, 256>>>();
    scatter_kernel<<<EB, 256>>>(ei);

    // 3 GIN layers
    int hin[3]  = { SEL_X, SEL_H0, SEL_H1 };
    int hout[3] = { SEL_H0, SEL_H1, SEL_H2 };
    for (int l = 0; l < 3; l++) {
        agg_kernel<<<AB, 256>>>(hin[l], eps, l);
        mma_gemm_kernel<<<GB, 256>>>(SEL_T, 2 * l,     b1 + l * 128, SEL_Z);
        mma_gemm_kernel<<<GB, 256>>>(SEL_Z, 2 * l + 1, b2 + l * 128, hout[l]);
    }
    final_gemm_kernel<<<GB, 256>>>(fb, out);
}

// round 6
// speedup vs baseline: 1.6621x; 1.0042x over previous
#include <cuda_runtime.h>
#include <cuda_bf16.h>

#define N_NODES 50000
#define N_EDGES 640000
#define NELEM (N_NODES * 128)
#define NBLK 196

// ---------------- scratch (device globals) ----------------
__device__ __align__(16) __nv_bfloat16 g_xhi[NELEM], g_xlo[NELEM];
__device__ __align__(16) __nv_bfloat16 g_thi[NELEM], g_tlo[NELEM];
__device__ __align__(16) __nv_bfloat16 g_zhi[NELEM], g_zlo[NELEM];
__device__ __align__(16) __nv_bfloat16 g_hhi[3][NELEM], g_hlo[3][NELEM];
__device__ __align__(16) __nv_bfloat16 g_wthi[6][128 * 128], g_wtlo[6][128 * 128];
__device__ __align__(16) __nv_bfloat16 g_fwthi[128 * 512], g_fwtlo[128 * 512];
__device__ int g_rowptr[N_NODES + 1], g_cnt[N_NODES], g_cnt2[N_NODES], g_srcs[N_EDGES];
__device__ int g_is64, g_bsum[256], g_boff[256];

#define SEL_X 0
#define SEL_T 1
#define SEL_Z 2
#define SEL_H0 3
#define SEL_H1 4
#define SEL_H2 5

__device__ __forceinline__ void sel_hl(int s, const __nv_bfloat16*& hi,
                                       const __nv_bfloat16*& lo) {
    switch (s) {
        case SEL_X: hi = g_xhi; lo = g_xlo; break;
        case SEL_T: hi = g_thi; lo = g_tlo; break;
        case SEL_Z: hi = g_zhi; lo = g_zlo; break;
        case SEL_H0: hi = g_hhi[0]; lo = g_hlo[0]; break;
        case SEL_H1: hi = g_hhi[1]; lo = g_hlo[1]; break;
        default:     hi = g_hhi[2]; lo = g_hlo[2]; break;
    }
}
__device__ __forceinline__ void sel_out(int s, __nv_bfloat16*& hi, __nv_bfloat16*& lo) {
    switch (s) {
        case SEL_T: hi = g_thi; lo = g_tlo; break;
        case SEL_Z: hi = g_zhi; lo = g_zlo; break;
        case SEL_H0: hi = g_hhi[0]; lo = g_hlo[0]; break;
        case SEL_H1: hi = g_hhi[1]; lo = g_hlo[1]; break;
        default:     hi = g_hhi[2]; lo = g_hlo[2]; break;
    }
}

// ---------------- CSR build ----------------
__global__ void detect_zero_kernel(const int* __restrict__ ei32) {
    int i = blockIdx.x * 256 + threadIdx.x;
    if (i < N_NODES) g_cnt[i] = 0;
    if (blockIdx.x == 0 && threadIdx.x == 0) {
        int ornz = 0;
#pragma unroll
        for (int k = 0; k < 64; k++) ornz |= ei32[2 * k + 1];
        g_is64 = (ornz == 0) ? 1 : 0;
    }
}
__device__ __forceinline__ int edge_val(const int* ei32, int is64, long long idx) {
    return is64 ? ei32[2 * idx] : ei32[idx];
}
__global__ void hist_kernel(const int* __restrict__ ei32) {
    int e = blockIdx.x * blockDim.x + threadIdx.x;
    if (e < N_EDGES) {
        int dst = edge_val(ei32, g_is64, (long long)N_EDGES + e);
        if ((unsigned)dst < (unsigned)N_NODES) atomicAdd(&g_cnt[dst], 1);
    }
}
__global__ void bsum_kernel() {
    __shared__ int sh[256];
    int t = threadIdx.x, i = blockIdx.x * 256 + t;
    if (i < N_NODES) g_cnt2[i] = 0;
    sh[t] = (i < N_NODES) ? g_cnt[i] : 0;
    __syncthreads();
#pragma unroll
    for (int off = 128; off > 0; off >>= 1) {
        if (t < off) sh[t] += sh[t + off];
        __syncthreads();
    }
    if (t == 0) g_bsum[blockIdx.x] = sh[0];
}
__global__ void bscan_kernel() {
    __shared__ int sh[256];
    int t = threadIdx.x;
    int v = (t < NBLK) ? g_bsum[t] : 0;
    sh[t] = v;
    __syncthreads();
#pragma unroll
    for (int off = 1; off < 256; off <<= 1) {
        int a = (t >= off) ? sh[t - off] : 0;
        __syncthreads();
        sh[t] += a;
        __syncthreads();
    }
    g_boff[t] = sh[t] - v;
    if (t == 255) g_rowptr[N_NODES] = sh[255];
}
__global__ void rowptr_kernel() {
    __shared__ int sh[256];
    int t = threadIdx.x, i = blockIdx.x * 256 + t;
    int v = (i < N_NODES) ? g_cnt[i] : 0;
    sh[t] = v;
    __syncthreads();
#pragma unroll
    for (int off = 1; off < 256; off <<= 1) {
        int a = (t >= off) ? sh[t - off] : 0;
        __syncthreads();
        sh[t] += a;
        __syncthreads();
    }
    if (i < N_NODES) g_rowptr[i] = g_boff[blockIdx.x] + sh[t] - v;
}
__global__ void scatter_kernel(const int* __restrict__ ei32) {
    int e = blockIdx.x * blockDim.x + threadIdx.x;
    if (e < N_EDGES) {
        int is64 = g_is64;
        int src = edge_val(ei32, is64, e);
        int dst = edge_val(ei32, is64, (long long)N_EDGES + e);
        if ((unsigned)dst < (unsigned)N_NODES && (unsigned)src < (unsigned)N_NODES) {
            int pos = g_rowptr[dst] + atomicAdd(&g_cnt2[dst], 1);
            if ((unsigned)pos < (unsigned)N_EDGES) g_srcs[pos] = src;
        }
    }
}

// ---------------- x split ----------------
__global__ void split_x_kernel(const float* __restrict__ x) {
    int i = blockIdx.x * 256 + threadIdx.x;   // 8 floats per thread
    if (i >= NELEM / 8) return;
    const float4* xp = (const float4*)x;
    float4 v0 = xp[2 * i], v1 = xp[2 * i + 1];
    float v[8] = {v0.x, v0.y, v0.z, v0.w, v1.x, v1.y, v1.z, v1.w};
    uint4 hp, lp;
    __nv_bfloat162* h2 = (__nv_bfloat162*)&hp;
    __nv_bfloat162* l2 = (__nv_bfloat162*)&lp;
#pragma unroll
    for (int j = 0; j < 4; j++) {
        __nv_bfloat16 h0 = __float2bfloat16_rn(v[2 * j]);
        __nv_bfloat16 h1 = __float2bfloat16_rn(v[2 * j + 1]);
        h2[j].x = h0; h2[j].y = h1;
        l2[j].x = __float2bfloat16_rn(v[2 * j] - __bfloat162float(h0));
        l2[j].y = __float2bfloat16_rn(v[2 * j + 1] - __bfloat162float(h1));
    }
    ((uint4*)g_xhi)[i] = hp;
    ((uint4*)g_xlo)[i] = lp;
}

// ---------------- weight transpose + split ----------------
__global__ void wprep_kernel(const float* __restrict__ W1, const float* __restrict__ W2,
                             const float* __restrict__ fw) {
    int e = blockIdx.x * 256 + threadIdx.x;
    if (e < 6 * 16384) {
        int m = e >> 14, t = e & 16383;
        int n = t >> 7, k = t & 127;
        int l = m >> 1;
        const float* src = (m & 1) ? W2 : W1;
        float v = src[l * 16384 + k * 128 + n];
        __nv_bfloat16 h = __float2bfloat16_rn(v);
        g_wthi[m][n * 128 + k] = h;
        g_wtlo[m][n * 128 + k] = __float2bfloat16_rn(v - __bfloat162float(h));
    } else if (e < 6 * 16384 + 128 * 512) {
        int t = e - 6 * 16384;
        int n = t >> 9, k = t & 511;
        float v = fw[k * 128 + n];
        __nv_bfloat16 h = __float2bfloat16_rn(v);
        g_fwthi[n * 512 + k] = h;
        g_fwtlo[n * 512 + k] = __float2bfloat16_rn(v - __bfloat162float(h));
    }
}

// ---------------- aggregation: t = (1+eps)*h + segsum (hi/lo pairs) ---------
__global__ void agg_kernel(int hsel, const float* __restrict__ eps, int l) {
    const __nv_bfloat16 *hib, *lob;
    sel_hl(hsel, hib, lob);
    int wnode = (blockIdx.x * blockDim.x + threadIdx.x) >> 5;
    int lane = threadIdx.x & 31;
    if (wnode >= N_NODES) return;
    int half = lane >> 4;            // 0: hi array, 1: lo array
    int p = lane & 15;               // 16B chunk within 256B row
    const uint4* rows = (const uint4*)(half ? lob : hib);   // 16 uint4 per row
    float acc[8];
#pragma unroll
    for (int j = 0; j < 8; j++) acc[j] = 0.f;

    int beg = g_rowptr[wnode], end = g_rowptr[wnode + 1];
    int i = beg;
    for (; i + 2 <= end; i += 2) {
        int s0 = g_srcs[i], s1 = g_srcs[i + 1];
        uint4 v0 = rows[s0 * 16 + p];
        uint4 v1 = rows[s1 * 16 + p];
        const __nv_bfloat162* p0 = (const __nv_bfloat162*)&v0;
        const __nv_bfloat162* p1 = (const __nv_bfloat162*)&v1;
#pragma unroll
        for (int j = 0; j < 4; j++) {
            float2 f0 = __bfloat1622float2(p0[j]);
            float2 f1 = __bfloat1622float2(p1[j]);
            acc[2 * j] += f0.x + f1.x;
            acc[2 * j + 1] += f0.y + f1.y;
        }
    }
    for (; i < end; i++) {
        uint4 v = rows[g_srcs[i] * 16 + p];
        const __nv_bfloat162* pv = (const __nv_bfloat162*)&v;
#pragma unroll
        for (int j = 0; j < 4; j++) {
            float2 f = __bfloat1622float2(pv[j]);
            acc[2 * j] += f.x;
            acc[2 * j + 1] += f.y;
        }
    }
    // self term (this half's contribution; combines to (1+eps)*(hi+lo))
    float e = 1.0f + eps[l];
    {
        uint4 v = rows[wnode * 16 + p];
        const __nv_bfloat162* pv = (const __nv_bfloat162*)&v;
#pragma unroll
        for (int j = 0; j < 4; j++) {
            float2 f = __bfloat1622float2(pv[j]);
            acc[2 * j] += e * f.x;
            acc[2 * j + 1] += e * f.y;
        }
    }
    // combine halves
    float tot[8];
#pragma unroll
    for (int j = 0; j < 8; j++)
        tot[j] = acc[j] + __shfl_xor_sync(0xffffffffu, acc[j], 16);
    // split & store
    uint4 outv;
    __nv_bfloat162* o2 = (__nv_bfloat162*)&outv;
#pragma unroll
    for (int j = 0; j < 4; j++) {
        __nv_bfloat16 h0 = __float2bfloat16_rn(tot[2 * j]);
        __nv_bfloat16 h1 = __float2bfloat16_rn(tot[2 * j + 1]);
        if (half == 0) { o2[j].x = h0; o2[j].y = h1; }
        else {
            o2[j].x = __float2bfloat16_rn(tot[2 * j] - __bfloat162float(h0));
            o2[j].y = __float2bfloat16_rn(tot[2 * j + 1] - __bfloat162float(h1));
        }
    }
    uint4* dst = (uint4*)(half ? g_tlo : g_thi);
    dst[wnode * 16 + p] = outv;
}

// ---------------- tensor-core GEMM machinery ----------------
__device__ __forceinline__ void cp16(unsigned s, const void* g, bool pred) {
    int sz = pred ? 16 : 0;
    asm volatile("cp.async.cg.shared.global [%0], [%1], 16, %2;\n"
                 :: "r"(s), "l"(g), "r"(sz));
}
__device__ __forceinline__ void cp_commit() { asm volatile("cp.async.commit_group;\n"); }
__device__ __forceinline__ void cp_wait0()  { asm volatile("cp.async.wait_group 0;\n" ::: "memory"); }

__device__ __forceinline__ void ldsm4(unsigned* r, unsigned addr) {
    asm volatile("ldmatrix.sync.aligned.m8n8.x4.shared.b16 {%0,%1,%2,%3}, [%4];"
                 : "=r"(r[0]), "=r"(r[1]), "=r"(r[2]), "=r"(r[3]) : "r"(addr));
}
__device__ __forceinline__ void mma_bf16(float* c, const unsigned* a, const unsigned* b) {
    asm volatile(
        "mma.sync.aligned.m16n8k16.row.col.f32.bf16.bf16.f32 "
        "{%0,%1,%2,%3},{%4,%5,%6,%7},{%8,%9},{%0,%1,%2,%3};"
        : "+f"(c[0]), "+f"(c[1]), "+f"(c[2]), "+f"(c[3])
        : "r"(a[0]), "r"(a[1]), "r"(a[2]), "r"(a[3]), "r"(b[0]), "r"(b[1]));
}
__device__ __forceinline__ void store_hl(__nv_bfloat16* Ohi, __nv_bfloat16* Olo,
                                         long long off, float v0, float v1) {
    __nv_bfloat16 h0 = __float2bfloat16_rn(v0), h1 = __float2bfloat16_rn(v1);
    __nv_bfloat162 hp; hp.x = h0; hp.y = h1;
    *(__nv_bfloat162*)(Ohi + off) = hp;
    __nv_bfloat162 lp;
    lp.x = __float2bfloat16_rn(v0 - __bfloat162float(h0));
    lp.y = __float2bfloat16_rn(v1 - __bfloat162float(h1));
    *(__nv_bfloat162*)(Olo + off) = lp;
}

// smem: [stage][mat 0=Ahi 1=Alo 2=Whi 3=Wlo][128 rows * 24 bf16 (48B, pad)]
#define SM_ROW 24

// compute one k16 chunk (all 3 split products)
__device__ __forceinline__ void mma_chunk(const unsigned sb[4], int aoff0, int aoff1,
                                          const int* woff, float acc[2][8][4]) {
    unsigned ah[2][4], al[2][4];
    ldsm4(ah[0], sb[0] + aoff0);
    ldsm4(ah[1], sb[0] + aoff1);
    ldsm4(al[0], sb[1] + aoff0);
    ldsm4(al[1], sb[1] + aoff1);
#pragma unroll
    for (int ng = 0; ng < 4; ng++) {
        unsigned bh[4], bl[4];
        ldsm4(bh, sb[2] + woff[ng]);
        ldsm4(bl, sb[3] + woff[ng]);
#pragma unroll
        for (int mi = 0; mi < 2; mi++)
#pragma unroll
            for (int ns = 0; ns < 2; ns++) {
                float* C = acc[mi][ng * 2 + ns];
                mma_bf16(C, ah[mi], &bh[ns * 2]);
                mma_bf16(C, ah[mi], &bl[ns * 2]);
                mma_bf16(C, al[mi], &bh[ns * 2]);
            }
    }
}

// ---------------- layer GEMM: out = relu(A @ W + bias), K=128 ----------------
__global__ void __launch_bounds__(256, 2)
mma_gemm_kernel(int a_sel, int w_idx, const float* __restrict__ bias, int o_sel) {
    __shared__ __nv_bfloat16 sm[2][4][128 * SM_ROW];
    const __nv_bfloat16 *Ahi, *Alo;
    sel_hl(a_sel, Ahi, Alo);
    __nv_bfloat16 *Ohi, *Olo;
    sel_out(o_sel, Ohi, Olo);
    const __nv_bfloat16* Whi = g_wthi[w_idx];
    const __nv_bfloat16* Wlo = g_wtlo[w_idx];

    const int tid = threadIdx.x, lane = tid & 31, w = tid >> 5;
    const int wm = w & 3, wn = w >> 2;
    const int rowBase = blockIdx.x * 128;
    const int crow = tid >> 1, chalf = tid & 1;
    const int g = lane >> 3, r = lane & 7;

    unsigned sb[2][4];
#pragma unroll
    for (int st = 0; st < 2; st++)
#pragma unroll
        for (int m = 0; m < 4; m++)
            sb[st][m] = (unsigned)__cvta_generic_to_shared(sm[st][m]);

    const int aoff0 = (wm * 32 + 0 + (g & 1) * 8 + r) * 48 + (g >> 1) * 16;
    const int aoff1 = (wm * 32 + 16 + (g & 1) * 8 + r) * 48 + (g >> 1) * 16;
    int woff[4];
#pragma unroll
    for (int ng = 0; ng < 4; ng++)
        woff[ng] = (wn * 64 + ng * 16 + (g >> 1) * 8 + r) * 48 + (g & 1) * 16;

    float acc[2][8][4];
#pragma unroll
    for (int i = 0; i < 2; i++)
#pragma unroll
        for (int j = 0; j < 8; j++)
#pragma unroll
            for (int q = 0; q < 4; q++) acc[i][j][q] = 0.f;

    const unsigned dsto = (unsigned)(crow * 48 + chalf * 16);
    bool aok = (rowBase + crow) < N_NODES;
    const long long arow = (long long)(rowBase + crow) * 128;

    // prologue chunk 0
    cp16(sb[0][0] + dsto, Ahi + arow + chalf * 8, aok);
    cp16(sb[0][1] + dsto, Alo + arow + chalf * 8, aok);
    cp16(sb[0][2] + dsto, Whi + crow * 128 + chalf * 8, true);
    cp16(sb[0][3] + dsto, Wlo + crow * 128 + chalf * 8, true);
    cp_commit(); cp_wait0(); __syncthreads();

#pragma unroll
    for (int c = 0; c < 8; c++) {
        if (c < 7) {
            int kb = (c + 1) * 16 + chalf * 8;
            int st = (c + 1) & 1;
            cp16(sb[st][0] + dsto, Ahi + arow + kb, aok);
            cp16(sb[st][1] + dsto, Alo + arow + kb, aok);
            cp16(sb[st][2] + dsto, Whi + crow * 128 + kb, true);
            cp16(sb[st][3] + dsto, Wlo + crow * 128 + kb, true);
            cp_commit();
        }
        mma_chunk(sb[c & 1], aoff0, aoff1, woff, acc);
        cp_wait0();
        __syncthreads();
    }

    // epilogue: bias + relu, split-store
#pragma unroll
    for (int ni = 0; ni < 8; ni++) {
        int n0 = wn * 64 + ni * 8 + 2 * (lane & 3);
        float2 bv = *(const float2*)&bias[n0];
#pragma unroll
        for (int mi = 0; mi < 2; mi++) {
            int r0 = rowBase + wm * 32 + mi * 16 + (lane >> 2);
            float* C = acc[mi][ni];
            float v0 = fmaxf(C[0] + bv.x, 0.f), v1 = fmaxf(C[1] + bv.y, 0.f);
            float v2 = fmaxf(C[2] + bv.x, 0.f), v3 = fmaxf(C[3] + bv.y, 0.f);
            if (r0 < N_NODES) store_hl(Ohi, Olo, (long long)r0 * 128 + n0, v0, v1);
            if (r0 + 8 < N_NODES) store_hl(Ohi, Olo, (long long)(r0 + 8) * 128 + n0, v2, v3);
        }
    }
}

// ---------------- final GEMM: out = concat(x,h0,h1,h2) @ fw + fb, K=512 ------
__device__ __forceinline__ void final_src(int s, const __nv_bfloat16*& hi,
                                          const __nv_bfloat16*& lo) {
    switch (s) {
        case 0: hi = g_xhi; lo = g_xlo; break;
        case 1: hi = g_hhi[0]; lo = g_hlo[0]; break;
        case 2: hi = g_hhi[1]; lo = g_hlo[1]; break;
        default: hi = g_hhi[2]; lo = g_hlo[2]; break;
    }
}

__global__ void __launch_bounds__(256, 2)
final_gemm_kernel(const float* __restrict__ fb, float* __restrict__ out) {
    __shared__ __nv_bfloat16 sm[2][4][128 * SM_ROW];
    const int tid = threadIdx.x, lane = tid & 31, w = tid >> 5;
    const int wm = w & 3, wn = w >> 2;
    const int rowBase = blockIdx.x * 128;
    const int crow = tid >> 1, chalf = tid & 1;
    const int g = lane >> 3, r = lane & 7;

    unsigned sb[2][4];
#pragma unroll
    for (int st = 0; st < 2; st++)
#pragma unroll
        for (int m = 0; m < 4; m++)
            sb[st][m] = (unsigned)__cvta_generic_to_shared(sm[st][m]);

    const int aoff0 = (wm * 32 + 0 + (g & 1) * 8 + r) * 48 + (g >> 1) * 16;
    const int aoff1 = (wm * 32 + 16 + (g & 1) * 8 + r) * 48 + (g >> 1) * 16;
    int woff[4];
#pragma unroll
    for (int ng = 0; ng < 4; ng++)
        woff[ng] = (wn * 64 + ng * 16 + (g >> 1) * 8 + r) * 48 + (g & 1) * 16;

    float acc[2][8][4];
#pragma unroll
    for (int i = 0; i < 2; i++)
#pragma unroll
        for (int j = 0; j < 8; j++)
#pragma unroll
            for (int q = 0; q < 4; q++) acc[i][j][q] = 0.f;

    const unsigned dsto = (unsigned)(crow * 48 + chalf * 16);
    bool aok = (rowBase + crow) < N_NODES;
    const long long arow = (long long)(rowBase + crow) * 128;

    // prologue chunk 0 (source 0 = x)
    {
        const __nv_bfloat16 *shi, *slo;
        final_src(0, shi, slo);
        cp16(sb[0][0] + dsto, shi + arow + chalf * 8, aok);
        cp16(sb[0][1] + dsto, slo + arow + chalf * 8, aok);
        cp16(sb[0][2] + dsto, g_fwthi + crow * 512 + chalf * 8, true);
        cp16(sb[0][3] + dsto, g_fwtlo + crow * 512 + chalf * 8, true);
        cp_commit(); cp_wait0(); __syncthreads();
    }

    for (int c = 0; c < 32; c++) {
        if (c < 31) {
            int cn = c + 1;
            const __nv_bfloat16 *shi, *slo;
            final_src(cn >> 3, shi, slo);
            int kl = (cn & 7) * 16 + chalf * 8;
            int kw = cn * 16 + chalf * 8;
            int st = cn & 1;
            cp16(sb[st][0] + dsto, shi + arow + kl, aok);
            cp16(sb[st][1] + dsto, slo + arow + kl, aok);
            cp16(sb[st][2] + dsto, g_fwthi + crow * 512 + kw, true);
            cp16(sb[st][3] + dsto, g_fwtlo + crow * 512 + kw, true);
            cp_commit();
        }
        mma_chunk(sb[c & 1], aoff0, aoff1, woff, acc);
        cp_wait0();
        __syncthreads();
    }

#pragma unroll
    for (int ni = 0; ni < 8; ni++) {
        int n0 = wn * 64 + ni * 8 + 2 * (lane & 3);
        float2 bv = *(const float2*)&fb[n0];
#pragma unroll
        for (int mi = 0; mi < 2; mi++) {
            int r0 = rowBase + wm * 32 + mi * 16 + (lane >> 2);
            float* C = acc[mi][ni];
            if (r0 < N_NODES) {
                float2 o = make_float2(C[0] + bv.x, C[1] + bv.y);
                *(float2*)&out[(long long)r0 * 128 + n0] = o;
            }
            if (r0 + 8 < N_NODES) {
                float2 o = make_float2(C[2] + bv.x, C[3] + bv.y);
                *(float2*)&out[(long long)(r0 + 8) * 128 + n0] = o;
            }
        }
    }
}

// ---------------- launch ----------------
extern "C" void kernel_launch(void* const* d_in, const int* in_sizes, int n_in,
                              void* d_out, int out_size) {
    const float* x   = (const float*)d_in[0];
    const int*   ei  = (const int*)d_in[1];
    const float* W1  = (const float*)d_in[2];
    const float* b1  = (const float*)d_in[3];
    const float* W2  = (const float*)d_in[4];
    const float* b2  = (const float*)d_in[5];
    const float* eps = (const float*)d_in[6];
    const float* fw  = (const float*)d_in[7];
    const float* fb  = (const float*)d_in[8];
    float* out = (float*)d_out;

    const int EB = (N_EDGES + 255) / 256;
    const int GB = (N_NODES + 127) / 128;        // 391
    const int AB = (N_NODES * 32 + 255) / 256;   // warp per node

    // CSR build + input prep
    detect_zero_kernel<<<NBLK, 256>>>(ei);
    split_x_kernel<<<(NELEM / 8 + 255) / 256, 256>>>(x);
    wprep_kernel<<<(6 * 16384 + 128 * 512 + 255) / 256, 256>>>(W1, W2, fw);
    hist_kernel<<<EB, 256>>>(ei);
    bsum_kernel<<<NBLK, 256>>>();
    bscan_kernel<<<1, 256>>>();
    rowptr_kernel<<<NBLK, 256>>>();
    scatter_kernel<<<EB, 256>>>(ei);

    // 3 GIN layers
    int hin[3]  = { SEL_X, SEL_H0, SEL_H1 };
    int hout[3] = { SEL_H0, SEL_H1, SEL_H2 };
    for (int l = 0; l < 3; l++) {
        agg_kernel<<<AB, 256>>>(hin[l], eps, l);
        mma_gemm_kernel<<<GB, 256>>>(SEL_T, 2 * l,     b1 + l * 128, SEL_Z);
        mma_gemm_kernel<<<GB, 256>>>(SEL_Z, 2 * l + 1, b2 + l * 128, hout[l]);
    }
    final_gemm_kernel<<<GB, 256>>>(fb, out);
}